// round 5
// baseline (speedup 1.0000x reference)
#include <cuda_runtime.h>
#include <cuda_bf16.h>

// Problem constants (fixed by the reference setup)
#define N_NODES 150000
#define N_EDGE  2400000
#define DIM     64          // NINP
#define HID     128         // NHID
#define N_TOK   12800       // B*L = 64*200
#define NB1024  ((N_NODES + 1023) / 1024)   // 147 scan blocks
#define EB4     ((N_EDGE / 4 + 255) / 256)  // 2344 blocks for 4-edge/thread passes
#define FLAGB   (N_TOK / 256)               // 50

// ---------------------------------------------------------------------------
// Scratch (device globals; no allocations allowed)
// ---------------------------------------------------------------------------
__device__ __align__(256) int   g_count[N_NODES];     // in-degree (histogram)
__device__ __align__(256) int   g_rowstart[N_NODES];  // CSR row offsets
__device__ __align__(256) int   g_cursor[N_NODES];    // bucket cursors for build
__device__ __align__(256) int   g_bsum[NB1024];       // scan block sums
__device__ __align__(256) int   g_boff[NB1024];       // scanned block offsets
__device__ __align__(256) int   g_csrc[N_EDGE];       // CSR src indices, grouped by dst
__device__ __align__(256) float g_dinv[N_NODES];      // rsqrt(deg+1)
__device__ __align__(256) float g_cvec[N_NODES];      // raw: sum dinv_src; final: cvec
__device__ __align__(256) int   g_flag[N_NODES];      // output-node bitmap
__device__ __align__(256) int   g_need[N_NODES];      // nodes whose Y row is consumed
__device__ __align__(256) float g_E[(size_t)N_NODES * DIM];  // E' = dinv * emb
__device__ __align__(256) float g_Y[(size_t)N_NODES * DIM];  // Y' = dinv * (A_hat*emb)
__device__ __align__(256) float g_Z[(size_t)N_NODES * DIM];  // A_hat^2 * emb (flag rows)
__device__ __align__(256) float g_W[DIM * DIM];       // W1 @ W2
__device__ __align__(256) float g_bW[DIM];            // b1 @ W2

// ---------------------------------------------------------------------------
// K0: zero per-node state (graph replays -> must reset every launch)
// ---------------------------------------------------------------------------
__global__ void k_init(void) {
    int i = blockIdx.x * blockDim.x + threadIdx.x;
    if (i >= N_NODES) return;
    g_count[i] = 0;
    g_flag[i]  = 0;
    g_need[i]  = 0;
    g_cvec[i]  = 0.0f;
}

// ---------------------------------------------------------------------------
// K1 (fused): histogram (4 edges/thread) + flag + weight product.
// Disjoint block ranges; all outputs independent.
// ---------------------------------------------------------------------------
__global__ void k_hist_flag_w(const int* __restrict__ ei, const int* __restrict__ inp,
                              const float* __restrict__ W1, const float* __restrict__ b1,
                              const float* __restrict__ W2) {
    int bid = blockIdx.x;
    int tid = threadIdx.x;
    if (bid < EB4) {
        int e4 = bid * 256 + tid;
        if (e4 >= N_EDGE / 4) return;
        int4 d = ((const int4*)(ei + N_EDGE))[e4];
        atomicAdd(&g_count[d.x], 1);
        atomicAdd(&g_count[d.y], 1);
        atomicAdd(&g_count[d.z], 1);
        atomicAdd(&g_count[d.w], 1);
    } else if (bid < EB4 + FLAGB) {
        int t = (bid - EB4) * 256 + tid;
        g_flag[inp[t]] = 1;
    } else {
        for (int idx = tid; idx < DIM * DIM; idx += 256) {
            int i = idx >> 6, j = idx & 63;
            float s = 0.0f;
            #pragma unroll 8
            for (int m = 0; m < HID; m++) s += W1[i * HID + m] * W2[m * DIM + j];
            g_W[idx] = s;
        }
        if (tid < DIM) {
            float s = 0.0f;
            #pragma unroll 8
            for (int m = 0; m < HID; m++) s += b1[m] * W2[m * DIM + tid];
            g_bW[tid] = s;
        }
    }
}

// ---------------------------------------------------------------------------
// K2: per-block exclusive scan of g_count (1024 elems / block)
// ---------------------------------------------------------------------------
__global__ void k_scan_local(void) {
    __shared__ int sh[256];
    int tid = threadIdx.x;
    int base = blockIdx.x * 1024 + tid * 4;

    int c[4], ts = 0;
    #pragma unroll
    for (int k = 0; k < 4; k++) {
        int i = base + k;
        c[k] = (i < N_NODES) ? g_count[i] : 0;
        ts += c[k];
    }
    sh[tid] = ts;
    __syncthreads();
    for (int off = 1; off < 256; off <<= 1) {
        int v = (tid >= off) ? sh[tid - off] : 0;
        __syncthreads();
        sh[tid] += v;
        __syncthreads();
    }
    int run = sh[tid] - ts;
    #pragma unroll
    for (int k = 0; k < 4; k++) {
        int i = base + k;
        if (i < N_NODES) g_rowstart[i] = run;
        run += c[k];
    }
    if (tid == 255) g_bsum[blockIdx.x] = sh[255];
}

// K3: exclusive scan of the 147 block sums (one block)
__global__ void k_scan_bsum(void) {
    __shared__ int sh[256];
    int tid = threadIdx.x;
    int v = (tid < NB1024) ? g_bsum[tid] : 0;
    int orig = v;
    sh[tid] = v;
    __syncthreads();
    for (int off = 1; off < 256; off <<= 1) {
        int w = (tid >= off) ? sh[tid - off] : 0;
        __syncthreads();
        sh[tid] += w;
        __syncthreads();
    }
    if (tid < NB1024) g_boff[tid] = sh[tid] - orig;
}

// ---------------------------------------------------------------------------
// K4 (fused): finalize rowstart/cursor, dinv = rsqrt(deg+1), E' = dinv*emb.
// 16 threads per node (one float4 each).
// ---------------------------------------------------------------------------
__global__ void k_finalize_scale(const float* __restrict__ emb) {
    long long t = (long long)blockIdx.x * blockDim.x + threadIdx.x;
    if (t >= (long long)N_NODES * 16) return;
    int node = (int)(t >> 4);
    int part = (int)(t & 15);
    float di = rsqrtf((float)g_count[node] + 1.0f);
    if (part == 0) {
        int rs = g_rowstart[node] + g_boff[node >> 10];
        g_rowstart[node] = rs;
        g_cursor[node]   = rs;
        g_dinv[node]     = di;
    }
    float4 v = ((const float4*)emb)[t];
    v.x *= di; v.y *= di; v.z *= di; v.w *= di;
    ((float4*)g_E)[t] = v;
}

// ---------------------------------------------------------------------------
// K5: CSR build (4 edges/thread) — scatter src + accumulate row sums
// ---------------------------------------------------------------------------
__global__ void k_build(const int* __restrict__ ei) {
    int e4 = blockIdx.x * blockDim.x + threadIdx.x;
    if (e4 >= N_EDGE / 4) return;
    int4 s = ((const int4*)ei)[e4];
    int4 d = ((const int4*)(ei + N_EDGE))[e4];
    int p;
    p = atomicAdd(&g_cursor[d.x], 1); g_csrc[p] = s.x; atomicAdd(&g_cvec[d.x], g_dinv[s.x]);
    p = atomicAdd(&g_cursor[d.y], 1); g_csrc[p] = s.y; atomicAdd(&g_cvec[d.y], g_dinv[s.y]);
    p = atomicAdd(&g_cursor[d.z], 1); g_csrc[p] = s.z; atomicAdd(&g_cvec[d.z], g_dinv[s.z]);
    p = atomicAdd(&g_cursor[d.w], 1); g_csrc[p] = s.w; atomicAdd(&g_cvec[d.w], g_dinv[s.w]);
}

// ---------------------------------------------------------------------------
// K6: need = flag ∪ { src of edges into flagged nodes }. Warp per node.
// ---------------------------------------------------------------------------
__global__ void k_need(void) {
    int warp = (blockIdx.x * blockDim.x + threadIdx.x) >> 5;
    int lane = threadIdx.x & 31;
    if (warp >= N_NODES) return;
    if (!g_flag[warp]) return;
    if (lane == 0) g_need[warp] = 1;
    int rs  = g_rowstart[warp];
    int cnt = g_count[warp];
    for (int e = lane; e < cnt; e += 32)
        g_need[g_csrc[rs + e]] = 1;
}

// ---------------------------------------------------------------------------
// K7: gather pass 1 (needed rows only), weight-free:
//   Y'[i] = dinv_i^2 * ( E'[i] + sum_{src->i} E'[src] )
//   cvec[i] = dinv_i * ( dinv_i + raw_cvec[i] )
// One warp per node; lane owns 2 columns (float2). Unroll x4.
// ---------------------------------------------------------------------------
__global__ void k_gather1(void) {
    int node = (blockIdx.x * blockDim.x + threadIdx.x) >> 5;
    int lane = threadIdx.x & 31;
    if (node >= N_NODES) return;
    if (!g_need[node]) return;

    int rs  = g_rowstart[node];
    int cnt = g_count[node];
    float di = g_dinv[node];

    const float2* E2 = (const float2*)g_E;
    float2 acc = E2[(size_t)node * 32 + lane];   // self term

    int e = 0;
    for (; e + 4 <= cnt; e += 4) {
        int s0 = __ldg(&g_csrc[rs + e]);
        int s1 = __ldg(&g_csrc[rs + e + 1]);
        int s2 = __ldg(&g_csrc[rs + e + 2]);
        int s3 = __ldg(&g_csrc[rs + e + 3]);
        float2 v0 = E2[(size_t)s0 * 32 + lane];
        float2 v1 = E2[(size_t)s1 * 32 + lane];
        float2 v2 = E2[(size_t)s2 * 32 + lane];
        float2 v3 = E2[(size_t)s3 * 32 + lane];
        acc.x += (v0.x + v1.x) + (v2.x + v3.x);
        acc.y += (v0.y + v1.y) + (v2.y + v3.y);
    }
    for (; e < cnt; e++) {
        int s0 = __ldg(&g_csrc[rs + e]);
        float2 v0 = E2[(size_t)s0 * 32 + lane];
        acc.x += v0.x;
        acc.y += v0.y;
    }

    float s = di * di;
    acc.x *= s; acc.y *= s;
    ((float2*)g_Y)[(size_t)node * 32 + lane] = acc;
    if (lane == 0) g_cvec[node] = di * (di + g_cvec[node]);
}

// ---------------------------------------------------------------------------
// K8: gather pass 2 (flagged rows only): Z[n] = dinv_n * ( Y'[n] + sum Y'[src] )
// ---------------------------------------------------------------------------
__global__ void k_gather2(void) {
    int node = (blockIdx.x * blockDim.x + threadIdx.x) >> 5;
    int lane = threadIdx.x & 31;
    if (node >= N_NODES) return;
    if (!g_flag[node]) return;

    int rs  = g_rowstart[node];
    int cnt = g_count[node];
    float di = g_dinv[node];

    const float2* Y2 = (const float2*)g_Y;
    float2 acc = Y2[(size_t)node * 32 + lane];   // self term

    int e = 0;
    for (; e + 4 <= cnt; e += 4) {
        int s0 = __ldg(&g_csrc[rs + e]);
        int s1 = __ldg(&g_csrc[rs + e + 1]);
        int s2 = __ldg(&g_csrc[rs + e + 2]);
        int s3 = __ldg(&g_csrc[rs + e + 3]);
        float2 v0 = Y2[(size_t)s0 * 32 + lane];
        float2 v1 = Y2[(size_t)s1 * 32 + lane];
        float2 v2 = Y2[(size_t)s2 * 32 + lane];
        float2 v3 = Y2[(size_t)s3 * 32 + lane];
        acc.x += (v0.x + v1.x) + (v2.x + v3.x);
        acc.y += (v0.y + v1.y) + (v2.y + v3.y);
    }
    for (; e < cnt; e++) {
        int s0 = __ldg(&g_csrc[rs + e]);
        float2 v0 = Y2[(size_t)s0 * 32 + lane];
        acc.x += v0.x;
        acc.y += v0.y;
    }

    acc.x *= di; acc.y *= di;
    ((float2*)g_Z)[(size_t)node * 32 + lane] = acc;
}

// ---------------------------------------------------------------------------
// K9: final — out[t] = Z[idx_t] @ W + cvec[idx_t]*bW + b2
// ---------------------------------------------------------------------------
__global__ void k_final(const int* __restrict__ inp, const float* __restrict__ b2,
                        float* __restrict__ out) {
    __shared__ float Ws[DIM * DIM];
    __shared__ float Zs[4 * DIM];
    __shared__ float cs[4];

    int tid = threadIdx.x;
    int grp = tid >> 6;
    int j   = tid & 63;

    for (int idx = tid; idx < DIM * DIM; idx += 256) Ws[idx] = g_W[idx];

    int tok = blockIdx.x * 4 + grp;
    int node = inp[tok];
    Zs[grp * DIM + j] = g_Z[(size_t)node * DIM + j];
    if (j == 0) cs[grp] = g_cvec[node];
    __syncthreads();

    float acc = cs[grp] * g_bW[j] + b2[j];
    #pragma unroll 16
    for (int k = 0; k < DIM; k++)
        acc += Zs[grp * DIM + k] * Ws[k * DIM + j];
    out[(size_t)tok * DIM + j] = acc;
}

// ---------------------------------------------------------------------------
// Launcher
// Input order (metadata): 0 emb, 1 W1, 2 b1, 3 W2, 4 b2,
//                         5 input, 6 input_timestamp (unused), 7 edge_index
// NOTE: index tensors are int32 (JAX x64 disabled -> astype(int64) is a no-op).
// ---------------------------------------------------------------------------
extern "C" void kernel_launch(void* const* d_in, const int* in_sizes, int n_in,
                              void* d_out, int out_size) {
    const float* emb = (const float*)d_in[0];
    const float* W1  = (const float*)d_in[1];
    const float* b1  = (const float*)d_in[2];
    const float* W2  = (const float*)d_in[3];
    const float* b2  = (const float*)d_in[4];
    const int*   inp = (const int*)d_in[5];
    const int*   ei  = (const int*)d_in[7];
    float* out = (float*)d_out;

    const int T = 256;
    int nodeBlocks   = (N_NODES + T - 1) / T;                // 586
    int node16Blocks = (int)(((long long)N_NODES * 16 + T - 1) / T); // 9375
    int warpBlocks   = (N_NODES + (T / 32) - 1) / (T / 32);  // 18750

    k_init<<<nodeBlocks, T>>>();
    k_hist_flag_w<<<EB4 + FLAGB + 1, T>>>(ei, inp, W1, b1, W2);
    k_scan_local<<<NB1024, T>>>();
    k_scan_bsum<<<1, T>>>();
    k_finalize_scale<<<node16Blocks, T>>>(emb);
    k_build<<<EB4, T>>>(ei);
    k_need<<<warpBlocks, T>>>();
    k_gather1<<<warpBlocks, T>>>();
    k_gather2<<<warpBlocks, T>>>();
    k_final<<<N_TOK / 4, T>>>(inp, b2, out);
}

// round 6
// speedup vs baseline: 1.0623x; 1.0623x over previous
#include <cuda_runtime.h>
#include <cuda_bf16.h>
#include <limits.h>

// Problem constants (fixed by the reference setup)
#define N_NODES 150000
#define N_EDGE  2400000
#define DIM     64          // NINP
#define HID     128         // NHID
#define N_TOK   12800       // B*L = 64*200
#define NB1024  ((N_NODES + 1023) / 1024)   // 147 scan blocks
#define EB4     ((N_EDGE / 4 + 255) / 256)  // 2344 blocks for 4-edge/thread passes
#define FLAGB   (N_TOK / 256)               // 50

// ---------------------------------------------------------------------------
// Scratch (device globals; no allocations allowed)
// ---------------------------------------------------------------------------
__device__ __align__(256) int   g_count[N_NODES];     // in-degree (histogram)
__device__ __align__(256) int   g_rowstart[N_NODES];  // CSR row offsets
__device__ __align__(256) int   g_cursor[N_NODES];    // bucket cursors for build
__device__ __align__(256) int   g_agg[NB1024];        // scan aggregates (lookback)
__device__ __align__(256) int   g_csrc[N_EDGE];       // CSR src indices, grouped by dst
__device__ __align__(256) float g_dinv[N_NODES];      // rsqrt(deg+1)
__device__ __align__(256) float g_cvec[N_NODES];      // cvec for flagged nodes
__device__ __align__(256) int   g_flag[N_NODES];      // output-node bitmap
__device__ __align__(256) int   g_need[N_NODES];      // nodes whose Y row is consumed
__device__ __align__(256) int   g_list[N_TOK];        // compact list of unique flagged nodes
__device__ int g_nlist;                               // count of unique flagged nodes
__device__ __align__(256) float g_E[(size_t)N_NODES * DIM];  // E' = dinv * emb
__device__ __align__(256) float g_Y[(size_t)N_NODES * DIM];  // Y' = dinv * (A_hat*emb)
__device__ __align__(256) float g_Z[(size_t)N_NODES * DIM];  // A_hat^2 * emb (flag rows)
__device__ __align__(256) float g_W[DIM * DIM];       // W1 @ W2
__device__ __align__(256) float g_bW[DIM];            // b1 @ W2

// ---------------------------------------------------------------------------
// K0: zero per-node state (graph replays -> must reset every launch)
// ---------------------------------------------------------------------------
__global__ void k_init(void) {
    int i = blockIdx.x * blockDim.x + threadIdx.x;
    if (i >= N_NODES) return;
    g_count[i] = 0;
    g_flag[i]  = 0;
    g_need[i]  = 0;
    if (i < NB1024) g_agg[i] = INT_MIN;
    if (i == 0) g_nlist = 0;
}

// ---------------------------------------------------------------------------
// K1 (fused): histogram (4 edges/thread) + flag/list + weight product.
// Disjoint block ranges; all outputs independent.
// ---------------------------------------------------------------------------
__global__ void k_hist_flag_w(const int* __restrict__ ei, const int* __restrict__ inp,
                              const float* __restrict__ W1, const float* __restrict__ b1,
                              const float* __restrict__ W2) {
    int bid = blockIdx.x;
    int tid = threadIdx.x;
    if (bid < EB4) {
        int e4 = bid * 256 + tid;
        if (e4 >= N_EDGE / 4) return;
        int4 d = ((const int4*)(ei + N_EDGE))[e4];
        atomicAdd(&g_count[d.x], 1);
        atomicAdd(&g_count[d.y], 1);
        atomicAdd(&g_count[d.z], 1);
        atomicAdd(&g_count[d.w], 1);
    } else if (bid < EB4 + FLAGB) {
        int t = (bid - EB4) * 256 + tid;   // FLAGB*256 == N_TOK exactly
        int n = inp[t];
        if (atomicExch(&g_flag[n], 1) == 0) {
            int p = atomicAdd(&g_nlist, 1);
            g_list[p] = n;
        }
    } else {
        for (int idx = tid; idx < DIM * DIM; idx += 256) {
            int i = idx >> 6, j = idx & 63;
            float s = 0.0f;
            #pragma unroll 8
            for (int m = 0; m < HID; m++) s += W1[i * HID + m] * W2[m * DIM + j];
            g_W[idx] = s;
        }
        if (tid < DIM) {
            float s = 0.0f;
            #pragma unroll 8
            for (int m = 0; m < HID; m++) s += b1[m] * W2[m * DIM + tid];
            g_bW[tid] = s;
        }
    }
}

// ---------------------------------------------------------------------------
// K2 (fused): single-pass exclusive scan (decoupled lookback, 147 co-resident
// blocks) -> rowstart/cursor, then dinv + E' = dinv*emb for this block's nodes.
// ---------------------------------------------------------------------------
__global__ void k_scan_fused(const float* __restrict__ emb) {
    __shared__ int sh[256];
    __shared__ int s_prefix;
    int tid = threadIdx.x;
    int b   = blockIdx.x;
    int base = b * 1024 + tid * 4;

    // local counts + per-thread sum
    int c[4], ts = 0;
    #pragma unroll
    for (int k = 0; k < 4; k++) {
        int i = base + k;
        c[k] = (i < N_NODES) ? g_count[i] : 0;
        ts += c[k];
    }
    sh[tid] = ts;
    __syncthreads();
    for (int off = 1; off < 256; off <<= 1) {
        int v = (tid >= off) ? sh[tid - off] : 0;
        __syncthreads();
        sh[tid] += v;
        __syncthreads();
    }

    // publish this block's aggregate
    if (tid == 0) atomicExch(&g_agg[b], sh[255]);

    // lookback: warp 0 sums all predecessor aggregates (lane-parallel spin)
    if (tid < 32) {
        int sum = 0;
        for (int j = b - 1 - tid; j >= 0; j -= 32) {
            int v;
            do { v = atomicAdd(&g_agg[j], 0); } while (v == INT_MIN);
            sum += v;
        }
        #pragma unroll
        for (int off = 16; off; off >>= 1) sum += __shfl_xor_sync(0xffffffffu, sum, off);
        if (tid == 0) s_prefix = sum;
    }
    __syncthreads();

    int run = s_prefix + sh[tid] - ts;   // global exclusive prefix for this chunk
    #pragma unroll
    for (int k = 0; k < 4; k++) {
        int i = base + k;
        if (i < N_NODES) { g_rowstart[i] = run; g_cursor[i] = run; }
        run += c[k];
    }

    // part 2: dinv + E scaling for nodes [b*1024, b*1024+1024)
    long long t0 = (long long)b * 1024 * 16;
    for (int k = tid; k < 1024 * 16; k += 256) {
        long long t = t0 + k;
        int node = (int)(t >> 4);
        if (node >= N_NODES) break;
        float di = rsqrtf((float)g_count[node] + 1.0f);
        if ((k & 15) == 0) g_dinv[node] = di;
        float4 v = ((const float4*)emb)[t];
        v.x *= di; v.y *= di; v.z *= di; v.w *= di;
        ((float4*)g_E)[t] = v;
    }
}

// ---------------------------------------------------------------------------
// K3: CSR build (4 edges/thread) — pure int scatter
// ---------------------------------------------------------------------------
__global__ void k_build(const int* __restrict__ ei) {
    int e4 = blockIdx.x * blockDim.x + threadIdx.x;
    if (e4 >= N_EDGE / 4) return;
    int4 s = ((const int4*)ei)[e4];
    int4 d = ((const int4*)(ei + N_EDGE))[e4];
    g_csrc[atomicAdd(&g_cursor[d.x], 1)] = s.x;
    g_csrc[atomicAdd(&g_cursor[d.y], 1)] = s.y;
    g_csrc[atomicAdd(&g_cursor[d.z], 1)] = s.z;
    g_csrc[atomicAdd(&g_cursor[d.w], 1)] = s.w;
}

// ---------------------------------------------------------------------------
// K4: need = flagged ∪ { src of edges into flagged }. Warp per list entry.
// ---------------------------------------------------------------------------
__global__ void k_need(void) {
    int w    = (blockIdx.x * blockDim.x + threadIdx.x) >> 5;
    int lane = threadIdx.x & 31;
    if (w >= g_nlist) return;
    int node = g_list[w];
    if (lane == 0) g_need[node] = 1;
    int rs  = g_rowstart[node];
    int cnt = g_count[node];
    for (int e = lane; e < cnt; e += 32)
        g_need[g_csrc[rs + e]] = 1;
}

// ---------------------------------------------------------------------------
// K5: gather pass 1 (needed rows only), weight-free:
//   Y'[i] = dinv_i^2 * ( E'[i] + sum_{src->i} E'[src] )
// One warp per node; lane owns 2 columns (float2). Unroll x4.
// ---------------------------------------------------------------------------
__global__ void k_gather1(void) {
    int node = (blockIdx.x * blockDim.x + threadIdx.x) >> 5;
    int lane = threadIdx.x & 31;
    if (node >= N_NODES) return;
    if (!g_need[node]) return;

    int rs  = g_rowstart[node];
    int cnt = g_count[node];
    float di = g_dinv[node];

    const float2* E2 = (const float2*)g_E;
    float2 acc = E2[(size_t)node * 32 + lane];   // self term

    int e = 0;
    for (; e + 4 <= cnt; e += 4) {
        int s0 = __ldg(&g_csrc[rs + e]);
        int s1 = __ldg(&g_csrc[rs + e + 1]);
        int s2 = __ldg(&g_csrc[rs + e + 2]);
        int s3 = __ldg(&g_csrc[rs + e + 3]);
        float2 v0 = E2[(size_t)s0 * 32 + lane];
        float2 v1 = E2[(size_t)s1 * 32 + lane];
        float2 v2 = E2[(size_t)s2 * 32 + lane];
        float2 v3 = E2[(size_t)s3 * 32 + lane];
        acc.x += (v0.x + v1.x) + (v2.x + v3.x);
        acc.y += (v0.y + v1.y) + (v2.y + v3.y);
    }
    for (; e < cnt; e++) {
        int s0 = __ldg(&g_csrc[rs + e]);
        float2 v0 = E2[(size_t)s0 * 32 + lane];
        acc.x += v0.x;
        acc.y += v0.y;
    }

    float s = di * di;
    acc.x *= s; acc.y *= s;
    ((float2*)g_Y)[(size_t)node * 32 + lane] = acc;
}

// ---------------------------------------------------------------------------
// K6: gather pass 2 over the compact flagged list:
//   Z[n]    = dinv_n * ( Y'[n] + sum Y'[src] )
//   cvec[n] = dinv_n * ( dinv_n + sum dinv_src )   (warp-uniform loads, free)
// ---------------------------------------------------------------------------
__global__ void k_gather2(void) {
    int w    = (blockIdx.x * blockDim.x + threadIdx.x) >> 5;
    int lane = threadIdx.x & 31;
    if (w >= g_nlist) return;
    int node = g_list[w];

    int rs  = g_rowstart[node];
    int cnt = g_count[node];
    float di = g_dinv[node];

    const float2* Y2 = (const float2*)g_Y;
    float2 acc = Y2[(size_t)node * 32 + lane];   // self term
    float  cs  = di;                             // dinv_n self part

    int e = 0;
    for (; e + 4 <= cnt; e += 4) {
        int s0 = __ldg(&g_csrc[rs + e]);
        int s1 = __ldg(&g_csrc[rs + e + 1]);
        int s2 = __ldg(&g_csrc[rs + e + 2]);
        int s3 = __ldg(&g_csrc[rs + e + 3]);
        float2 v0 = Y2[(size_t)s0 * 32 + lane];
        float2 v1 = Y2[(size_t)s1 * 32 + lane];
        float2 v2 = Y2[(size_t)s2 * 32 + lane];
        float2 v3 = Y2[(size_t)s3 * 32 + lane];
        acc.x += (v0.x + v1.x) + (v2.x + v3.x);
        acc.y += (v0.y + v1.y) + (v2.y + v3.y);
        cs += (g_dinv[s0] + g_dinv[s1]) + (g_dinv[s2] + g_dinv[s3]);
    }
    for (; e < cnt; e++) {
        int s0 = __ldg(&g_csrc[rs + e]);
        float2 v0 = Y2[(size_t)s0 * 32 + lane];
        acc.x += v0.x;
        acc.y += v0.y;
        cs += g_dinv[s0];
    }

    acc.x *= di; acc.y *= di;
    ((float2*)g_Z)[(size_t)node * 32 + lane] = acc;
    if (lane == 0) g_cvec[node] = di * cs;
}

// ---------------------------------------------------------------------------
// K7: final — out[t] = Z[idx_t] @ W + cvec[idx_t]*bW + b2
// ---------------------------------------------------------------------------
__global__ void k_final(const int* __restrict__ inp, const float* __restrict__ b2,
                        float* __restrict__ out) {
    __shared__ float Ws[DIM * DIM];
    __shared__ float Zs[4 * DIM];
    __shared__ float cs[4];

    int tid = threadIdx.x;
    int grp = tid >> 6;
    int j   = tid & 63;

    for (int idx = tid; idx < DIM * DIM; idx += 256) Ws[idx] = g_W[idx];

    int tok = blockIdx.x * 4 + grp;
    int node = inp[tok];
    Zs[grp * DIM + j] = g_Z[(size_t)node * DIM + j];
    if (j == 0) cs[grp] = g_cvec[node];
    __syncthreads();

    float acc = cs[grp] * g_bW[j] + b2[j];
    #pragma unroll 16
    for (int k = 0; k < DIM; k++)
        acc += Zs[grp * DIM + k] * Ws[k * DIM + j];
    out[(size_t)tok * DIM + j] = acc;
}

// ---------------------------------------------------------------------------
// Launcher
// Input order (metadata): 0 emb, 1 W1, 2 b1, 3 W2, 4 b2,
//                         5 input, 6 input_timestamp (unused), 7 edge_index
// NOTE: index tensors are int32 (JAX x64 disabled -> astype(int64) is a no-op).
// ---------------------------------------------------------------------------
extern "C" void kernel_launch(void* const* d_in, const int* in_sizes, int n_in,
                              void* d_out, int out_size) {
    const float* emb = (const float*)d_in[0];
    const float* W1  = (const float*)d_in[1];
    const float* b1  = (const float*)d_in[2];
    const float* W2  = (const float*)d_in[3];
    const float* b2  = (const float*)d_in[4];
    const int*   inp = (const int*)d_in[5];
    const int*   ei  = (const int*)d_in[7];
    float* out = (float*)d_out;

    const int T = 256;
    int nodeBlocks = (N_NODES + T - 1) / T;                // 586
    int warpBlocks = (N_NODES + (T / 32) - 1) / (T / 32);  // 18750
    int listBlocks = N_TOK / (T / 32);                     // 1600 (warp per list slot)

    k_init<<<nodeBlocks, T>>>();
    k_hist_flag_w<<<EB4 + FLAGB + 1, T>>>(ei, inp, W1, b1, W2);
    k_scan_fused<<<NB1024, T>>>(emb);
    k_build<<<EB4, T>>>(ei);
    k_need<<<listBlocks, T>>>();
    k_gather1<<<warpBlocks, T>>>();
    k_gather2<<<listBlocks, T>>>();
    k_final<<<N_TOK / 4, T>>>(inp, b2, out);
}